// round 13
// baseline (speedup 1.0000x reference)
#include <cuda_runtime.h>
#include <cstdint>
#include <cfloat>

// Problem constants: z (2,64,8,64,64), embedding (4096,64)
#define CH 64
#define SPA 32768
#define NTOK 65536
#define KCODE 4096
#define OUT_ELEMS 4194304
#define TBLK 64
#define NBLK (NTOK / TBLK)      // 1024

// kB smem byte offsets (16B aligned)
#define OFF_WSM 0               // pre_w [o][c]                  16384
#define OFF_BSM 16384           // pre_b                           256
#define OFF_ZSM 16640           // z tile [64 c][64 tok] f       16384
#define OFF_TSM 33024           // t tile [64 c][64 tok] ull dup 32768
#define OFF_ESM 65792           // e chunks 2 x [64 c][128 k] f  65536
#define OFF_E2  131328          // e2 2 x 128 f                   1024
#define OFF_RV  132352          // argmin vals [8 w][64 t]        2048
#define OFF_RI  134400          // argmin idxs [8 w][64 t]        2048
#define OFF_IDX 136448          // final idx [64]                  256
#define OFF_LSM 136704          // loss partials [4][64]          1024
#define SMTOT   137728          // > 113.5KB => exactly 1 CTA/SM

typedef unsigned long long ull;

// -------- static device scratch (no cudaMalloc allowed) --------
__device__ __align__(16) float g_eT[KCODE / 128][64][128];   // [chunk][c][k]
__device__ __align__(16) float g_e2[KCODE];
__device__ __align__(16) float g_pe[KCODE * CH];             // emb @ post_w^T + post_b
__device__ float g_part[NBLK];
__device__ unsigned g_done;                                  // zero-init; reset by last block

// -------- helpers (proven R2/R10/R11/R12) --------
__device__ __forceinline__ uint32_t smem_u32(const void* p) {
    uint32_t a;
    asm("{ .reg .u64 t; cvta.to.shared.u64 t, %1; cvt.u32.u64 %0, t; }" : "=r"(a) : "l"(p));
    return a;
}
__device__ __forceinline__ void cpa16(uint32_t dst, const void* src) {
    asm volatile("cp.async.cg.shared.global [%0], [%1], 16;" :: "r"(dst), "l"(src) : "memory");
}
#define CP_COMMIT() asm volatile("cp.async.commit_group;" ::: "memory")
#define CP_WAIT0()  asm volatile("cp.async.wait_group 0;" ::: "memory")
#define CP_WAIT1()  asm volatile("cp.async.wait_group 1;" ::: "memory")

__device__ __forceinline__ ull ffma2(ull a, ull b, ull c) {
    ull d;
    asm("fma.rn.f32x2 %0, %1, %2, %3;" : "=l"(d) : "l"(a), "l"(b), "l"(c));
    return d;
}
__device__ __forceinline__ ull dup2(float x) {
    ull d;
    unsigned u = __float_as_uint(x);
    asm("mov.b64 %0, {%1, %2};" : "=l"(d) : "r"(u), "r"(u));
    return d;
}
__device__ __forceinline__ float f2lo(ull v) { return __uint_as_float((unsigned)v); }
__device__ __forceinline__ float f2hi(ull v) { return __uint_as_float((unsigned)(v >> 32)); }

// ============================================================================
// kP: pe = emb @ post_w^T + post_b ; e2 ; transposed codebook g_eT.
// 1024 blocks x 256 thr; 4 codes per block, one shot (proven ~5us).
// ============================================================================
__global__ void __launch_bounds__(256) kP(const float* __restrict__ emb,
                                          const float* __restrict__ post_w,
                                          const float* __restrict__ post_b) {
    __shared__ float wsm[64 * 65];
    __shared__ float esm[4][64];
    __shared__ float wred[4][2];
    int tid = threadIdx.x;
    int sub = tid >> 6;
    int o = tid & 63;
    int wh = (tid >> 5) & 1;
    int k = blockIdx.x * 4 + sub;

    for (int i = tid; i < 4096; i += 256)
        wsm[(i >> 6) * 65 + (i & 63)] = post_w[i];

    float v = emb[k * 64 + o];
    esm[sub][o] = v;
    float sq = v * v;
#pragma unroll
    for (int off = 16; off; off >>= 1)
        sq += __shfl_xor_sync(0xffffffffu, sq, off);
    if ((tid & 31) == 0) wred[sub][wh] = sq;
    __syncthreads();

    float acc = post_b[o];
#pragma unroll
    for (int c = 0; c < 64; c++)
        acc = fmaf(esm[sub][c], wsm[o * 65 + c], acc);
    g_pe[k * 64 + o] = acc;
    g_eT[k >> 7][o][k & 127] = v;
    if (o == 0) g_e2[k] = wred[sub][0] + wred[sub][1];
}

// ============================================================================
// kB: fused pre-conv + exact fp32 FFMA2 argmin + loss/gather/output epilogue
//     + last-block deterministic loss reduction.
// 1024 CTAs x 256 thr; 64 tokens/CTA; 1 CTA/SM -> 7 waves @98.9%.
// t stored PRE-DUPLICATED (ull) in smem: one LDS.128 yields both tokens'
// f32x2-duplicated values -> zero dup-MOVs in the inner loop.
// Lane tx -> token pair (2tx,2tx+1); warp ty -> 16-code stripe.
// ============================================================================
__global__ void __launch_bounds__(256) kB(const float* __restrict__ z,
                                          const float* __restrict__ emb,
                                          const float* __restrict__ pre_w,
                                          const float* __restrict__ pre_b,
                                          float* __restrict__ dout) {
    extern __shared__ __align__(16) char sm[];
    uint32_t smb = smem_u32(sm);
    float* wsm  = (float*)(sm + OFF_WSM);
    float* bsm  = (float*)(sm + OFF_BSM);
    float* zsm  = (float*)(sm + OFF_ZSM);
    ull*   tsmd = (ull*)  (sm + OFF_TSM);
    float* rv   = (float*)(sm + OFF_RV);
    int*   ri   = (int*)  (sm + OFF_RI);
    int*   idxs = (int*)  (sm + OFF_IDX);
    float* lsm  = (float*)(sm + OFF_LSM);
    __shared__ int sLast;

    int tid = threadIdx.x;
    int ty = tid >> 5;              // warp: 16-code stripe
    int tx = tid & 31;              // lane: token pair (2tx, 2tx+1)
    int n0 = blockIdx.x * TBLK;
    int b  = n0 >> 15;
    int s0 = n0 & 32767;

    // ---- prologue cp.async: group0 = {w, b, z, chunk0, e2_0}; group1 = {chunk1, e2_1}
    const char* zb = (const char*)z + ((size_t)b * (CH * SPA) + s0) * 4;
#pragma unroll
    for (int it = 0; it < 4; it++)
        cpa16(smb + OFF_WSM + (tid + it * 256) * 16, (const char*)pre_w + (tid + it * 256) * 16);
    if (tid < 16) cpa16(smb + OFF_BSM + tid * 16, (const char*)pre_b + tid * 16);
#pragma unroll
    for (int it = 0; it < 4; it++) {
        int ix = tid + it * 256;    // 1024 segs: c = ix>>4, seg = ix&15
        cpa16(smb + OFF_ZSM + ix * 16, zb + (size_t)(ix >> 4) * SPA * 4 + (ix & 15) * 16);
    }
#pragma unroll
    for (int it = 0; it < 8; it++)
        cpa16(smb + OFF_ESM + (tid + it * 256) * 16, (const char*)g_eT + (tid + it * 256) * 16);
    if (tid < 32) cpa16(smb + OFF_E2 + tid * 16, (const char*)g_e2 + tid * 16);
    CP_COMMIT();
#pragma unroll
    for (int it = 0; it < 8; it++)
        cpa16(smb + OFF_ESM + 32768 + (tid + it * 256) * 16,
              (const char*)g_eT + 32768 + (tid + it * 256) * 16);
    if (tid < 32) cpa16(smb + OFF_E2 + 512 + tid * 16, (const char*)(g_e2 + 128) + tid * 16);
    CP_COMMIT();
    CP_WAIT1();                     // group0 landed
    __syncthreads();

    // ---- phase 0: pre-conv -> tsmd[c][tok] stored as duplicated f32x2 pairs
    {
        int g = tid >> 6;           // 0..3 -> 16 output channels
        int j = tid & 63;           // token
        float acc16[16];
#pragma unroll
        for (int o = 0; o < 16; o++) acc16[o] = bsm[g * 16 + o];
#pragma unroll 8
        for (int c = 0; c < 64; c++) {
            float zv = zsm[c * 64 + j];
#pragma unroll
            for (int o = 0; o < 16; o++)
                acc16[o] = fmaf(zv, wsm[(g * 16 + o) * 64 + c], acc16[o]);
        }
#pragma unroll
        for (int o = 0; o < 16; o++) tsmd[(g * 16 + o) * 64 + j] = dup2(acc16[o]);
    }
    __syncthreads();

    // ---- main loop: 32 chunks of 128 codes, exact fp32, double-buffered
    float best0 = FLT_MAX, best1 = FLT_MAX;
    int bi0 = 0x7fffffff, bi1 = 0x7fffffff;

    for (int i = 0; i < 32; i++) {
        if (i < 31) { CP_WAIT1(); } else { CP_WAIT0(); }
        __syncthreads();
        int buf = i & 1;
        const float* erow = (const float*)(sm + OFF_ESM + buf * 32768) + ty * 16;
        const float* e2b  = (const float*)(sm + OFF_E2 + buf * 512);

        ull acc[2][8];
#pragma unroll
        for (int t = 0; t < 2; t++)
#pragma unroll
            for (int j = 0; j < 8; j++) acc[t][j] = 0ull;

#pragma unroll 8
        for (int c = 0; c < 64; c++) {
            ulonglong2 tv = *(const ulonglong2*)(tsmd + c * 64 + 2 * tx);  // LDS.128: both dup pairs
            ull td0 = tv.x;
            ull td1 = tv.y;
            const ulonglong2* ep = (const ulonglong2*)(erow + c * 128);
            ulonglong2 ea = ep[0];      // codes 0..3 of my 16 (warp-uniform LDS)
            ulonglong2 eb = ep[1];      // codes 4..7
            const ulonglong2* ep2 = (const ulonglong2*)(erow + c * 128 + 8);
            ulonglong2 ec = ep2[0];     // codes 8..11
            ulonglong2 ed = ep2[1];     // codes 12..15
            acc[0][0] = ffma2(td0, ea.x, acc[0][0]);
            acc[1][0] = ffma2(td1, ea.x, acc[1][0]);
            acc[0][1] = ffma2(td0, ea.y, acc[0][1]);
            acc[1][1] = ffma2(td1, ea.y, acc[1][1]);
            acc[0][2] = ffma2(td0, eb.x, acc[0][2]);
            acc[1][2] = ffma2(td1, eb.x, acc[1][2]);
            acc[0][3] = ffma2(td0, eb.y, acc[0][3]);
            acc[1][3] = ffma2(td1, eb.y, acc[1][3]);
            acc[0][4] = ffma2(td0, ec.x, acc[0][4]);
            acc[1][4] = ffma2(td1, ec.x, acc[1][4]);
            acc[0][5] = ffma2(td0, ec.y, acc[0][5]);
            acc[1][5] = ffma2(td1, ec.y, acc[1][5]);
            acc[0][6] = ffma2(td0, ed.x, acc[0][6]);
            acc[1][6] = ffma2(td1, ed.x, acc[1][6]);
            acc[0][7] = ffma2(td0, ed.y, acc[0][7]);
            acc[1][7] = ffma2(td1, ed.y, acc[1][7]);
        }

        // score = e2 - 2*dot ; ascending k, strict < (jnp argmin tie-break)
        int kb = i * 128 + ty * 16;
#pragma unroll
        for (int j = 0; j < 8; j++) {
            float e2a = e2b[ty * 16 + 2 * j];
            float e2c = e2b[ty * 16 + 2 * j + 1];
            float sA0 = fmaf(f2lo(acc[0][j]), -2.0f, e2a);
            float sB0 = fmaf(f2hi(acc[0][j]), -2.0f, e2c);
            float sA1 = fmaf(f2lo(acc[1][j]), -2.0f, e2a);
            float sB1 = fmaf(f2hi(acc[1][j]), -2.0f, e2c);
            if (sA0 < best0) { best0 = sA0; bi0 = kb + 2 * j; }
            if (sB0 < best0) { best0 = sB0; bi0 = kb + 2 * j + 1; }
            if (sA1 < best1) { best1 = sA1; bi1 = kb + 2 * j; }
            if (sB1 < best1) { best1 = sB1; bi1 = kb + 2 * j + 1; }
        }

        __syncthreads();            // all warps done reading buf
        if (i + 2 < 32) {
            const char* es = (const char*)g_eT + (size_t)(i + 2) * 32768;
#pragma unroll
            for (int it = 0; it < 8; it++)
                cpa16(smb + OFF_ESM + buf * 32768 + (tid + it * 256) * 16,
                      es + (tid + it * 256) * 16);
            if (tid < 32)
                cpa16(smb + OFF_E2 + buf * 512 + tid * 16,
                      (const char*)(g_e2 + (i + 2) * 128) + tid * 16);
            CP_COMMIT();
        }
    }

    // ---- cross-warp argmin reduce per token (lowest-index tie-break)
    rv[ty * 64 + 2 * tx]     = best0;
    rv[ty * 64 + 2 * tx + 1] = best1;
    ri[ty * 64 + 2 * tx]     = bi0;
    ri[ty * 64 + 2 * tx + 1] = bi1;
    __syncthreads();
    if (tid < 64) {
        float bv = FLT_MAX;
        int bk = 0x7fffffff;
#pragma unroll
        for (int w = 0; w < 8; w++) {
            float v = rv[w * 64 + tid];
            int k = ri[w * 64 + tid];
            if (v < bv || (v == bv && k < bk)) { bv = v; bk = k; }
        }
        idxs[tid] = bk;
    }
    __syncthreads();

    // ---- fused output epilogue: loss partial + pe gather + idx out
    {
        int g = tid >> 6;           // 16 channels
        int j = tid & 63;           // token
        int myidx = idxs[j];
        const float4* er = (const float4*)(emb + (size_t)myidx * 64 + g * 16);
        const float4* pr = (const float4*)(g_pe + (size_t)myidx * 64 + g * 16);
        const float* tf = (const float*)tsmd;   // low float of each dup pair
        float lp = 0.0f;
        float* op = dout + (size_t)b * (CH * SPA) + (size_t)(g * 16) * SPA + s0 + j;
#pragma unroll
        for (int q4 = 0; q4 < 4; q4++) {
            float4 e4 = er[q4];
            float4 p4 = pr[q4];
            int o = q4 * 4;
            float d;
            d = e4.x - tf[((g * 16 + o + 0) * 64 + j) * 2]; lp = fmaf(d, d, lp);
            d = e4.y - tf[((g * 16 + o + 1) * 64 + j) * 2]; lp = fmaf(d, d, lp);
            d = e4.z - tf[((g * 16 + o + 2) * 64 + j) * 2]; lp = fmaf(d, d, lp);
            d = e4.w - tf[((g * 16 + o + 3) * 64 + j) * 2]; lp = fmaf(d, d, lp);
            op[(size_t)(o + 0) * SPA] = p4.x;
            op[(size_t)(o + 1) * SPA] = p4.y;
            op[(size_t)(o + 2) * SPA] = p4.z;
            op[(size_t)(o + 3) * SPA] = p4.w;
        }
        lsm[g * 64 + j] = lp;
        if (g == 0) dout[OUT_ELEMS + 2 + n0 + j] = (float)myidx;
    }
    __syncthreads();
    if (tid < 64) {
        float s = lsm[tid] + lsm[64 + tid] + lsm[128 + tid] + lsm[192 + tid];
        rv[tid] = s;
    }
    __syncthreads();
    if (tid == 0) {
        float s = 0.0f;
#pragma unroll
        for (int j = 0; j < 64; j++) s += rv[j];
        g_part[blockIdx.x] = s;
        __threadfence();
        unsigned v = atomicAdd(&g_done, 1u);
        sLast = (v == NBLK - 1) ? 1 : 0;
    }
    __syncthreads();

    // ---- last block: deterministic final loss reduction
    if (sLast) {
        __threadfence();
        float s = g_part[tid] + g_part[tid + 256] + g_part[tid + 512] + g_part[tid + 768];
        rv[tid] = s;
        __syncthreads();
#pragma unroll
        for (int st = 128; st > 0; st >>= 1) {
            if (tid < st) rv[tid] += rv[tid + st];
            __syncthreads();
        }
        if (tid == 0) {
            float m = rv[0] / (float)OUT_ELEMS;
            dout[OUT_ELEMS]     = m;   // codebook_loss
            dout[OUT_ELEMS + 1] = m;   // commitment_loss (same forward value)
            g_done = 0;                // reset for next graph replay
        }
    }
}

// ============================================================================
extern "C" void kernel_launch(void* const* d_in, const int* in_sizes, int n_in,
                              void* d_out, int out_size) {
    const float* z      = (const float*)d_in[0];
    const float* emb    = (const float*)d_in[1];
    const float* pre_w  = (const float*)d_in[2];
    const float* pre_b  = (const float*)d_in[3];
    const float* post_w = (const float*)d_in[4];
    const float* post_b = (const float*)d_in[5];
    float* dout = (float*)d_out;

    cudaFuncSetAttribute(kB, cudaFuncAttributeMaxDynamicSharedMemorySize, SMTOT);

    kP<<<KCODE / 4, 256>>>(emb, post_w, post_b);
    kB<<<NBLK, 256, SMTOT>>>(z, emb, pre_w, pre_b, dout);
}

// round 14
// speedup vs baseline: 1.2433x; 1.2433x over previous
#include <cuda_runtime.h>
#include <cstdint>
#include <cfloat>

// Problem constants: z (2,64,8,64,64), embedding (4096,64)
#define CH 64
#define SPA 32768
#define NTOK 65536
#define KCODE 4096
#define OUT_ELEMS 4194304
#define TBLK 64
#define NBLK (NTOK / TBLK)      // 1024

// kB smem byte offsets (16B aligned)
#define OFF_WSM 0               // pre_w [o][c]                  16384
#define OFF_BSM 16384           // pre_b                           256
#define OFF_ZSM 16640           // z tile [64 c][64 tok]         16384
#define OFF_TSM 33024           // t tile [64 c][64 tok]         16384
#define OFF_ESM 49408           // e chunks 2 x [64 c][128 k]    65536
#define OFF_E2  114944          // e2 2 x 128 f                   1024
#define OFF_RV  115968          // argmin vals [8 w][64 t]        2048
#define OFF_RI  118016          // argmin idxs [8 w][64 t]        2048
#define OFF_IDX 120064          // final idx [64]                  256
#define OFF_LSM 120320          // loss partials [4][64]          1024
#define SMTOT   121344          // > 113.5KB => exactly 1 CTA/SM

typedef unsigned long long ull;

// -------- static device scratch (no cudaMalloc allowed) --------
__device__ __align__(16) float g_eT[KCODE / 128][64][128];   // [chunk][c][k]
__device__ __align__(16) float g_e2[KCODE];
__device__ __align__(16) float g_pe[KCODE * CH];             // emb @ post_w^T + post_b
__device__ float g_part[NBLK];

// -------- helpers (proven R2/R9) --------
__device__ __forceinline__ uint32_t smem_u32(const void* p) {
    uint32_t a;
    asm("{ .reg .u64 t; cvta.to.shared.u64 t, %1; cvt.u32.u64 %0, t; }" : "=r"(a) : "l"(p));
    return a;
}
__device__ __forceinline__ void cpa16(uint32_t dst, const void* src) {
    asm volatile("cp.async.cg.shared.global [%0], [%1], 16;" :: "r"(dst), "l"(src) : "memory");
}
#define CP_COMMIT() asm volatile("cp.async.commit_group;" ::: "memory")
#define CP_WAIT0()  asm volatile("cp.async.wait_group 0;" ::: "memory")
#define CP_WAIT1()  asm volatile("cp.async.wait_group 1;" ::: "memory")

__device__ __forceinline__ ull ffma2(ull a, ull b, ull c) {
    ull d;
    asm("fma.rn.f32x2 %0, %1, %2, %3;" : "=l"(d) : "l"(a), "l"(b), "l"(c));
    return d;
}
__device__ __forceinline__ ull dup2(float x) {
    ull d;
    unsigned u = __float_as_uint(x);
    asm("mov.b64 %0, {%1, %2};" : "=l"(d) : "r"(u), "r"(u));
    return d;
}
__device__ __forceinline__ float f2lo(ull v) { return __uint_as_float((unsigned)v); }
__device__ __forceinline__ float f2hi(ull v) { return __uint_as_float((unsigned)(v >> 32)); }

// ============================================================================
// kP: pe = emb @ post_w^T + post_b ; e2 ; transposed codebook g_eT.
// 256 blocks x 256 thr; 4 codes in parallel (sub-blocks of 64 threads).
// ============================================================================
__global__ void __launch_bounds__(256) kP(const float* __restrict__ emb,
                                          const float* __restrict__ post_w,
                                          const float* __restrict__ post_b) {
    __shared__ float wsm[64 * 65];
    __shared__ float esm[4][64];
    __shared__ float wred[4][2];
    int tid = threadIdx.x;
    int sub = tid >> 6;
    int o = tid & 63;
    int wh = (tid >> 5) & 1;

    for (int i = tid; i < 4096; i += 256)
        wsm[(i >> 6) * 65 + (i & 63)] = post_w[i];
    float wb = post_b[o];

    for (int kk = 0; kk < 4; kk++) {
        int k = blockIdx.x * 16 + kk * 4 + sub;
        __syncthreads();
        float v = emb[k * 64 + o];
        esm[sub][o] = v;
        float sq = v * v;
#pragma unroll
        for (int off = 16; off; off >>= 1)
            sq += __shfl_xor_sync(0xffffffffu, sq, off);
        if ((tid & 31) == 0) wred[sub][wh] = sq;
        __syncthreads();
        float acc = wb;
#pragma unroll
        for (int c = 0; c < 64; c++)
            acc = fmaf(esm[sub][c], wsm[o * 65 + c], acc);
        g_pe[k * 64 + o] = acc;
        g_eT[k >> 7][o][k & 127] = v;
        if (o == 0) g_e2[k] = wred[sub][0] + wred[sub][1];
    }
}

// ============================================================================
// kB: fused pre-conv + exact fp32 FFMA2 argmin + loss/gather/output epilogue.
// 1024 CTAs x 256 thr; 64 tokens/CTA; 1 CTA/SM (smem-forced) -> 7 waves @98.9%.
// Main loop = R2's proven layout: lane tx -> token pair (2tx,2tx+1),
// warp ty -> 16-code stripe; e chunks double-buffered via cp.async.
// ============================================================================
__global__ void __launch_bounds__(256) kB(const float* __restrict__ z,
                                          const float* __restrict__ emb,
                                          const float* __restrict__ pre_w,
                                          const float* __restrict__ pre_b,
                                          float* __restrict__ dout) {
    extern __shared__ __align__(16) char sm[];
    uint32_t smb = smem_u32(sm);
    float* wsm  = (float*)(sm + OFF_WSM);
    float* bsm  = (float*)(sm + OFF_BSM);
    float* zsm  = (float*)(sm + OFF_ZSM);
    float* tsm  = (float*)(sm + OFF_TSM);
    float* rv   = (float*)(sm + OFF_RV);
    int*   ri   = (int*)  (sm + OFF_RI);
    int*   idxs = (int*)  (sm + OFF_IDX);
    float* lsm  = (float*)(sm + OFF_LSM);

    int tid = threadIdx.x;
    int ty = tid >> 5;              // warp: 16-code stripe
    int tx = tid & 31;              // lane: token pair (2tx, 2tx+1)
    int n0 = blockIdx.x * TBLK;
    int b  = n0 >> 15;
    int s0 = n0 & 32767;

    // ---- prologue cp.async: group0 = {w, b, z, e chunk0, e2_0}; group1 = {chunk1, e2_1}
    const char* zb = (const char*)z + ((size_t)b * (CH * SPA) + s0) * 4;
#pragma unroll
    for (int it = 0; it < 4; it++)
        cpa16(smb + OFF_WSM + (tid + it * 256) * 16, (const char*)pre_w + (tid + it * 256) * 16);
    if (tid < 16) cpa16(smb + OFF_BSM + tid * 16, (const char*)pre_b + tid * 16);
#pragma unroll
    for (int it = 0; it < 4; it++) {
        int ix = tid + it * 256;    // 1024 segs: c = ix>>4, seg = ix&15
        cpa16(smb + OFF_ZSM + ix * 16, zb + (size_t)(ix >> 4) * SPA * 4 + (ix & 15) * 16);
    }
#pragma unroll
    for (int it = 0; it < 8; it++)
        cpa16(smb + OFF_ESM + (tid + it * 256) * 16, (const char*)g_eT + (tid + it * 256) * 16);
    if (tid < 32) cpa16(smb + OFF_E2 + tid * 16, (const char*)g_e2 + tid * 16);
    CP_COMMIT();
#pragma unroll
    for (int it = 0; it < 8; it++)
        cpa16(smb + OFF_ESM + 32768 + (tid + it * 256) * 16,
              (const char*)g_eT + 32768 + (tid + it * 256) * 16);
    if (tid < 32) cpa16(smb + OFF_E2 + 512 + tid * 16, (const char*)(g_e2 + 128) + tid * 16);
    CP_COMMIT();
    CP_WAIT1();                     // group0 landed (w, b, z, chunk0, e2_0)
    __syncthreads();

    // ---- phase 0: pre-conv for this block's 64 tokens -> tsm[c][tok]
    {
        int g = tid >> 6;           // 0..3 -> 16 output channels
        int j = tid & 63;           // token
        float acc16[16];
#pragma unroll
        for (int o = 0; o < 16; o++) acc16[o] = bsm[g * 16 + o];
#pragma unroll 8
        for (int c = 0; c < 64; c++) {
            float zv = zsm[c * 64 + j];
#pragma unroll
            for (int o = 0; o < 16; o++)
                acc16[o] = fmaf(zv, wsm[(g * 16 + o) * 64 + c], acc16[o]);
        }
#pragma unroll
        for (int o = 0; o < 16; o++) tsm[(g * 16 + o) * 64 + j] = acc16[o];
    }
    __syncthreads();

    // ---- main loop: 32 chunks of 128 codes, exact fp32, double-buffered
    float best0 = FLT_MAX, best1 = FLT_MAX;
    int bi0 = 0x7fffffff, bi1 = 0x7fffffff;

    for (int i = 0; i < 32; i++) {
        if (i < 31) { CP_WAIT1(); } else { CP_WAIT0(); }
        __syncthreads();
        int buf = i & 1;
        const float* erow = (const float*)(sm + OFF_ESM + buf * 32768) + ty * 16;
        const float* e2b  = (const float*)(sm + OFF_E2 + buf * 512);

        ull acc[2][8];
#pragma unroll
        for (int t = 0; t < 2; t++)
#pragma unroll
            for (int j = 0; j < 8; j++) acc[t][j] = 0ull;

#pragma unroll 8
        for (int c = 0; c < 64; c++) {
            float2 tv = *(const float2*)(tsm + c * 64 + 2 * tx);
            ull td0 = dup2(tv.x);
            ull td1 = dup2(tv.y);
            const ulonglong2* ep = (const ulonglong2*)(erow + c * 128);
            ulonglong2 ea = ep[0];      // codes 0..3 of my 16 (warp-uniform LDS)
            ulonglong2 eb = ep[1];      // codes 4..7
            const ulonglong2* ep2 = (const ulonglong2*)(erow + c * 128 + 8);
            ulonglong2 ec = ep2[0];     // codes 8..11
            ulonglong2 ed = ep2[1];     // codes 12..15
            acc[0][0] = ffma2(td0, ea.x, acc[0][0]);
            acc[1][0] = ffma2(td1, ea.x, acc[1][0]);
            acc[0][1] = ffma2(td0, ea.y, acc[0][1]);
            acc[1][1] = ffma2(td1, ea.y, acc[1][1]);
            acc[0][2] = ffma2(td0, eb.x, acc[0][2]);
            acc[1][2] = ffma2(td1, eb.x, acc[1][2]);
            acc[0][3] = ffma2(td0, eb.y, acc[0][3]);
            acc[1][3] = ffma2(td1, eb.y, acc[1][3]);
            acc[0][4] = ffma2(td0, ec.x, acc[0][4]);
            acc[1][4] = ffma2(td1, ec.x, acc[1][4]);
            acc[0][5] = ffma2(td0, ec.y, acc[0][5]);
            acc[1][5] = ffma2(td1, ec.y, acc[1][5]);
            acc[0][6] = ffma2(td0, ed.x, acc[0][6]);
            acc[1][6] = ffma2(td1, ed.x, acc[1][6]);
            acc[0][7] = ffma2(td0, ed.y, acc[0][7]);
            acc[1][7] = ffma2(td1, ed.y, acc[1][7]);
        }

        // score = e2 - 2*dot ; ascending k, strict < (jnp argmin tie-break)
        int kb = i * 128 + ty * 16;
#pragma unroll
        for (int j = 0; j < 8; j++) {
            float e2a = e2b[ty * 16 + 2 * j];
            float e2c = e2b[ty * 16 + 2 * j + 1];
            float sA0 = fmaf(f2lo(acc[0][j]), -2.0f, e2a);
            float sB0 = fmaf(f2hi(acc[0][j]), -2.0f, e2c);
            float sA1 = fmaf(f2lo(acc[1][j]), -2.0f, e2a);
            float sB1 = fmaf(f2hi(acc[1][j]), -2.0f, e2c);
            if (sA0 < best0) { best0 = sA0; bi0 = kb + 2 * j; }
            if (sB0 < best0) { best0 = sB0; bi0 = kb + 2 * j + 1; }
            if (sA1 < best1) { best1 = sA1; bi1 = kb + 2 * j; }
            if (sB1 < best1) { best1 = sB1; bi1 = kb + 2 * j + 1; }
        }

        __syncthreads();            // all warps done reading buf
        if (i + 2 < 32) {
            const char* es = (const char*)g_eT + (size_t)(i + 2) * 32768;
#pragma unroll
            for (int it = 0; it < 8; it++)
                cpa16(smb + OFF_ESM + buf * 32768 + (tid + it * 256) * 16,
                      es + (tid + it * 256) * 16);
            if (tid < 32)
                cpa16(smb + OFF_E2 + buf * 512 + tid * 16,
                      (const char*)(g_e2 + (i + 2) * 128) + tid * 16);
            CP_COMMIT();
        }
    }

    // ---- cross-warp argmin reduce per token (lowest-index tie-break)
    rv[ty * 64 + 2 * tx]     = best0;
    rv[ty * 64 + 2 * tx + 1] = best1;
    ri[ty * 64 + 2 * tx]     = bi0;
    ri[ty * 64 + 2 * tx + 1] = bi1;
    __syncthreads();
    if (tid < 64) {
        float bv = FLT_MAX;
        int bk = 0x7fffffff;
#pragma unroll
        for (int w = 0; w < 8; w++) {
            float v = rv[w * 64 + tid];
            int k = ri[w * 64 + tid];
            if (v < bv || (v == bv && k < bk)) { bv = v; bk = k; }
        }
        idxs[tid] = bk;
    }
    __syncthreads();

    // ---- fused output epilogue: loss partial + pe gather + idx out
    {
        int g = tid >> 6;           // 16 channels
        int j = tid & 63;           // token
        int myidx = idxs[j];
        const float4* er = (const float4*)(emb + (size_t)myidx * 64 + g * 16);
        const float4* pr = (const float4*)(g_pe + (size_t)myidx * 64 + g * 16);
        float lp = 0.0f;
        float* op = dout + (size_t)b * (CH * SPA) + (size_t)(g * 16) * SPA + s0 + j;
#pragma unroll
        for (int q4 = 0; q4 < 4; q4++) {
            float4 e4 = er[q4];
            float4 p4 = pr[q4];
            int o = q4 * 4;
            float d;
            d = e4.x - tsm[(g * 16 + o + 0) * 64 + j]; lp = fmaf(d, d, lp);
            d = e4.y - tsm[(g * 16 + o + 1) * 64 + j]; lp = fmaf(d, d, lp);
            d = e4.z - tsm[(g * 16 + o + 2) * 64 + j]; lp = fmaf(d, d, lp);
            d = e4.w - tsm[(g * 16 + o + 3) * 64 + j]; lp = fmaf(d, d, lp);
            op[(size_t)(o + 0) * SPA] = p4.x;
            op[(size_t)(o + 1) * SPA] = p4.y;
            op[(size_t)(o + 2) * SPA] = p4.z;
            op[(size_t)(o + 3) * SPA] = p4.w;
        }
        lsm[g * 64 + j] = lp;
        if (g == 0) dout[OUT_ELEMS + 2 + n0 + j] = (float)myidx;
    }
    __syncthreads();
    if (tid < 64) {
        float s = lsm[tid] + lsm[64 + tid] + lsm[128 + tid] + lsm[192 + tid];
        rv[tid] = s;
    }
    __syncthreads();
    if (tid == 0) {
        float s = 0.0f;
#pragma unroll
        for (int j = 0; j < 64; j++) s += rv[j];
        g_part[blockIdx.x] = s;
    }
}

// ============================================================================
// kD: deterministic final loss reduction over 1024 block partials
// ============================================================================
__global__ void kD(float* __restrict__ dout) {
    __shared__ float red[256];
    int tid = threadIdx.x;
    float s = 0.0f;
#pragma unroll
    for (int j = 0; j < 4; j++) s += g_part[tid + j * 256];
    red[tid] = s;
    __syncthreads();
#pragma unroll
    for (int st = 128; st > 0; st >>= 1) {
        if (tid < st) red[tid] += red[tid + st];
        __syncthreads();
    }
    if (tid == 0) {
        float m = red[0] / (float)OUT_ELEMS;
        dout[OUT_ELEMS]     = m;   // codebook_loss
        dout[OUT_ELEMS + 1] = m;   // commitment_loss (same forward value)
    }
}

// ============================================================================
extern "C" void kernel_launch(void* const* d_in, const int* in_sizes, int n_in,
                              void* d_out, int out_size) {
    const float* z      = (const float*)d_in[0];
    const float* emb    = (const float*)d_in[1];
    const float* pre_w  = (const float*)d_in[2];
    const float* pre_b  = (const float*)d_in[3];
    const float* post_w = (const float*)d_in[4];
    const float* post_b = (const float*)d_in[5];
    float* dout = (float*)d_out;

    cudaFuncSetAttribute(kB, cudaFuncAttributeMaxDynamicSharedMemorySize, SMTOT);

    kP<<<KCODE / 16, 256>>>(emb, post_w, post_b);
    kB<<<NBLK, 256, SMTOT>>>(z, emb, pre_w, pre_b, dout);
    kD<<<1, 256>>>(dout);
}

// round 15
// speedup vs baseline: 1.2450x; 1.0013x over previous
#include <cuda_runtime.h>
#include <cstdint>
#include <cfloat>

// Problem constants: z (2,64,8,64,64), embedding (4096,64)
#define CH 64
#define SPA 32768
#define NTOK 65536
#define KCODE 4096
#define OUT_ELEMS 4194304
#define TBLK 64
#define NBLK (NTOK / TBLK)      // 1024

// kB smem byte offsets (16B aligned)
#define OFF_WSM 0               // pre_w [o][c]                  16384
#define OFF_BSM 16384           // pre_b                           256
#define OFF_ZSM 16640           // z tile [64 c][64 tok]         16384
#define OFF_TSM 33024           // t tile [64 c][64 tok]         16384
#define OFF_ESM 49408           // e chunks 2 x [64 c][128 k]    65536
#define OFF_E2  114944          // e2 2 x 128 f                   1024
#define OFF_RV  115968          // argmin vals [8 w][64 t]        2048
#define OFF_RI  118016          // argmin idxs [8 w][64 t]        2048
#define OFF_IDX 120064          // final idx [64]                  256
#define OFF_LSM 120320          // loss partials [4][64]          1024
#define SMTOT   121344          // > 113.5KB => exactly 1 CTA/SM

typedef unsigned long long ull;

// -------- static device scratch (no cudaMalloc allowed) --------
__device__ __align__(16) float g_eT[KCODE / 128][64][128];   // [chunk][c][k]
__device__ __align__(16) float g_e2[KCODE];
__device__ __align__(16) float g_pe[KCODE * CH];             // emb @ post_w^T + post_b
__device__ float g_part[NBLK];

// -------- helpers (proven R2/R10/R14) --------
__device__ __forceinline__ uint32_t smem_u32(const void* p) {
    uint32_t a;
    asm("{ .reg .u64 t; cvta.to.shared.u64 t, %1; cvt.u32.u64 %0, t; }" : "=r"(a) : "l"(p));
    return a;
}
__device__ __forceinline__ void cpa16(uint32_t dst, const void* src) {
    asm volatile("cp.async.cg.shared.global [%0], [%1], 16;" :: "r"(dst), "l"(src) : "memory");
}
#define CP_COMMIT() asm volatile("cp.async.commit_group;" ::: "memory")
#define CP_WAIT0()  asm volatile("cp.async.wait_group 0;" ::: "memory")
#define CP_WAIT1()  asm volatile("cp.async.wait_group 1;" ::: "memory")

__device__ __forceinline__ ull ffma2(ull a, ull b, ull c) {
    ull d;
    asm("fma.rn.f32x2 %0, %1, %2, %3;" : "=l"(d) : "l"(a), "l"(b), "l"(c));
    return d;
}
__device__ __forceinline__ ull dup2(float x) {
    ull d;
    unsigned u = __float_as_uint(x);
    asm("mov.b64 %0, {%1, %2};" : "=l"(d) : "r"(u), "r"(u));
    return d;
}
__device__ __forceinline__ float f2lo(ull v) { return __uint_as_float((unsigned)v); }
__device__ __forceinline__ float f2hi(ull v) { return __uint_as_float((unsigned)(v >> 32)); }

// ============================================================================
// kP: pe = emb @ post_w^T + post_b ; e2 ; transposed codebook g_eT.
// 1024 blocks x 256 thr; 4 codes per block, one shot (measured ~5us in R11).
// ============================================================================
__global__ void __launch_bounds__(256) kP(const float* __restrict__ emb,
                                          const float* __restrict__ post_w,
                                          const float* __restrict__ post_b) {
    __shared__ float wsm[64 * 65];
    __shared__ float esm[4][64];
    __shared__ float wred[4][2];
    int tid = threadIdx.x;
    int sub = tid >> 6;
    int o = tid & 63;
    int wh = (tid >> 5) & 1;
    int k = blockIdx.x * 4 + sub;

    for (int i = tid; i < 4096; i += 256)
        wsm[(i >> 6) * 65 + (i & 63)] = post_w[i];

    float v = emb[k * 64 + o];
    esm[sub][o] = v;
    float sq = v * v;
#pragma unroll
    for (int off = 16; off; off >>= 1)
        sq += __shfl_xor_sync(0xffffffffu, sq, off);
    if ((tid & 31) == 0) wred[sub][wh] = sq;
    __syncthreads();

    float acc = post_b[o];
#pragma unroll
    for (int c = 0; c < 64; c++)
        acc = fmaf(esm[sub][c], wsm[o * 65 + c], acc);
    g_pe[k * 64 + o] = acc;
    g_eT[k >> 7][o][k & 127] = v;
    if (o == 0) g_e2[k] = wred[sub][0] + wred[sub][1];
}

// ============================================================================
// kB: fused pre-conv + exact fp32 FFMA2 argmin + loss/gather/output epilogue.
// 1024 CTAs x 256 thr; 64 tokens/CTA; 1 CTA/SM (smem-forced) -> 7 waves @98.9%.
// Byte-identical to the R10/R14 measured optimum (861/862 us).
// Lane tx -> token pair (2tx,2tx+1); warp ty -> 16-code stripe;
// e chunks double-buffered via cp.async.
// ============================================================================
__global__ void __launch_bounds__(256) kB(const float* __restrict__ z,
                                          const float* __restrict__ emb,
                                          const float* __restrict__ pre_w,
                                          const float* __restrict__ pre_b,
                                          float* __restrict__ dout) {
    extern __shared__ __align__(16) char sm[];
    uint32_t smb = smem_u32(sm);
    float* wsm  = (float*)(sm + OFF_WSM);
    float* bsm  = (float*)(sm + OFF_BSM);
    float* zsm  = (float*)(sm + OFF_ZSM);
    float* tsm  = (float*)(sm + OFF_TSM);
    float* rv   = (float*)(sm + OFF_RV);
    int*   ri   = (int*)  (sm + OFF_RI);
    int*   idxs = (int*)  (sm + OFF_IDX);
    float* lsm  = (float*)(sm + OFF_LSM);

    int tid = threadIdx.x;
    int ty = tid >> 5;              // warp: 16-code stripe
    int tx = tid & 31;              // lane: token pair (2tx, 2tx+1)
    int n0 = blockIdx.x * TBLK;
    int b  = n0 >> 15;
    int s0 = n0 & 32767;

    // ---- prologue cp.async: group0 = {w, b, z, e chunk0, e2_0}; group1 = {chunk1, e2_1}
    const char* zb = (const char*)z + ((size_t)b * (CH * SPA) + s0) * 4;
#pragma unroll
    for (int it = 0; it < 4; it++)
        cpa16(smb + OFF_WSM + (tid + it * 256) * 16, (const char*)pre_w + (tid + it * 256) * 16);
    if (tid < 16) cpa16(smb + OFF_BSM + tid * 16, (const char*)pre_b + tid * 16);
#pragma unroll
    for (int it = 0; it < 4; it++) {
        int ix = tid + it * 256;    // 1024 segs: c = ix>>4, seg = ix&15
        cpa16(smb + OFF_ZSM + ix * 16, zb + (size_t)(ix >> 4) * SPA * 4 + (ix & 15) * 16);
    }
#pragma unroll
    for (int it = 0; it < 8; it++)
        cpa16(smb + OFF_ESM + (tid + it * 256) * 16, (const char*)g_eT + (tid + it * 256) * 16);
    if (tid < 32) cpa16(smb + OFF_E2 + tid * 16, (const char*)g_e2 + tid * 16);
    CP_COMMIT();
#pragma unroll
    for (int it = 0; it < 8; it++)
        cpa16(smb + OFF_ESM + 32768 + (tid + it * 256) * 16,
              (const char*)g_eT + 32768 + (tid + it * 256) * 16);
    if (tid < 32) cpa16(smb + OFF_E2 + 512 + tid * 16, (const char*)(g_e2 + 128) + tid * 16);
    CP_COMMIT();
    CP_WAIT1();                     // group0 landed (w, b, z, chunk0, e2_0)
    __syncthreads();

    // ---- phase 0: pre-conv for this block's 64 tokens -> tsm[c][tok]
    {
        int g = tid >> 6;           // 0..3 -> 16 output channels
        int j = tid & 63;           // token
        float acc16[16];
#pragma unroll
        for (int o = 0; o < 16; o++) acc16[o] = bsm[g * 16 + o];
#pragma unroll 8
        for (int c = 0; c < 64; c++) {
            float zv = zsm[c * 64 + j];
#pragma unroll
            for (int o = 0; o < 16; o++)
                acc16[o] = fmaf(zv, wsm[(g * 16 + o) * 64 + c], acc16[o]);
        }
#pragma unroll
        for (int o = 0; o < 16; o++) tsm[(g * 16 + o) * 64 + j] = acc16[o];
    }
    __syncthreads();

    // ---- main loop: 32 chunks of 128 codes, exact fp32, double-buffered
    float best0 = FLT_MAX, best1 = FLT_MAX;
    int bi0 = 0x7fffffff, bi1 = 0x7fffffff;

    for (int i = 0; i < 32; i++) {
        if (i < 31) { CP_WAIT1(); } else { CP_WAIT0(); }
        __syncthreads();
        int buf = i & 1;
        const float* erow = (const float*)(sm + OFF_ESM + buf * 32768) + ty * 16;
        const float* e2b  = (const float*)(sm + OFF_E2 + buf * 512);

        ull acc[2][8];
#pragma unroll
        for (int t = 0; t < 2; t++)
#pragma unroll
            for (int j = 0; j < 8; j++) acc[t][j] = 0ull;

#pragma unroll 8
        for (int c = 0; c < 64; c++) {
            float2 tv = *(const float2*)(tsm + c * 64 + 2 * tx);
            ull td0 = dup2(tv.x);
            ull td1 = dup2(tv.y);
            const ulonglong2* ep = (const ulonglong2*)(erow + c * 128);
            ulonglong2 ea = ep[0];      // codes 0..3 of my 16 (warp-uniform LDS)
            ulonglong2 eb = ep[1];      // codes 4..7
            const ulonglong2* ep2 = (const ulonglong2*)(erow + c * 128 + 8);
            ulonglong2 ec = ep2[0];     // codes 8..11
            ulonglong2 ed = ep2[1];     // codes 12..15
            acc[0][0] = ffma2(td0, ea.x, acc[0][0]);
            acc[1][0] = ffma2(td1, ea.x, acc[1][0]);
            acc[0][1] = ffma2(td0, ea.y, acc[0][1]);
            acc[1][1] = ffma2(td1, ea.y, acc[1][1]);
            acc[0][2] = ffma2(td0, eb.x, acc[0][2]);
            acc[1][2] = ffma2(td1, eb.x, acc[1][2]);
            acc[0][3] = ffma2(td0, eb.y, acc[0][3]);
            acc[1][3] = ffma2(td1, eb.y, acc[1][3]);
            acc[0][4] = ffma2(td0, ec.x, acc[0][4]);
            acc[1][4] = ffma2(td1, ec.x, acc[1][4]);
            acc[0][5] = ffma2(td0, ec.y, acc[0][5]);
            acc[1][5] = ffma2(td1, ec.y, acc[1][5]);
            acc[0][6] = ffma2(td0, ed.x, acc[0][6]);
            acc[1][6] = ffma2(td1, ed.x, acc[1][6]);
            acc[0][7] = ffma2(td0, ed.y, acc[0][7]);
            acc[1][7] = ffma2(td1, ed.y, acc[1][7]);
        }

        // score = e2 - 2*dot ; ascending k, strict < (jnp argmin tie-break)
        int kb = i * 128 + ty * 16;
#pragma unroll
        for (int j = 0; j < 8; j++) {
            float e2a = e2b[ty * 16 + 2 * j];
            float e2c = e2b[ty * 16 + 2 * j + 1];
            float sA0 = fmaf(f2lo(acc[0][j]), -2.0f, e2a);
            float sB0 = fmaf(f2hi(acc[0][j]), -2.0f, e2c);
            float sA1 = fmaf(f2lo(acc[1][j]), -2.0f, e2a);
            float sB1 = fmaf(f2hi(acc[1][j]), -2.0f, e2c);
            if (sA0 < best0) { best0 = sA0; bi0 = kb + 2 * j; }
            if (sB0 < best0) { best0 = sB0; bi0 = kb + 2 * j + 1; }
            if (sA1 < best1) { best1 = sA1; bi1 = kb + 2 * j; }
            if (sB1 < best1) { best1 = sB1; bi1 = kb + 2 * j + 1; }
        }

        __syncthreads();            // all warps done reading buf
        if (i + 2 < 32) {
            const char* es = (const char*)g_eT + (size_t)(i + 2) * 32768;
#pragma unroll
            for (int it = 0; it < 8; it++)
                cpa16(smb + OFF_ESM + buf * 32768 + (tid + it * 256) * 16,
                      es + (tid + it * 256) * 16);
            if (tid < 32)
                cpa16(smb + OFF_E2 + buf * 512 + tid * 16,
                      (const char*)(g_e2 + (i + 2) * 128) + tid * 16);
            CP_COMMIT();
        }
    }

    // ---- cross-warp argmin reduce per token (lowest-index tie-break)
    rv[ty * 64 + 2 * tx]     = best0;
    rv[ty * 64 + 2 * tx + 1] = best1;
    ri[ty * 64 + 2 * tx]     = bi0;
    ri[ty * 64 + 2 * tx + 1] = bi1;
    __syncthreads();
    if (tid < 64) {
        float bv = FLT_MAX;
        int bk = 0x7fffffff;
#pragma unroll
        for (int w = 0; w < 8; w++) {
            float v = rv[w * 64 + tid];
            int k = ri[w * 64 + tid];
            if (v < bv || (v == bv && k < bk)) { bv = v; bk = k; }
        }
        idxs[tid] = bk;
    }
    __syncthreads();

    // ---- fused output epilogue: loss partial + pe gather + idx out
    {
        int g = tid >> 6;           // 16 channels
        int j = tid & 63;           // token
        int myidx = idxs[j];
        const float4* er = (const float4*)(emb + (size_t)myidx * 64 + g * 16);
        const float4* pr = (const float4*)(g_pe + (size_t)myidx * 64 + g * 16);
        float lp = 0.0f;
        float* op = dout + (size_t)b * (CH * SPA) + (size_t)(g * 16) * SPA + s0 + j;
#pragma unroll
        for (int q4 = 0; q4 < 4; q4++) {
            float4 e4 = er[q4];
            float4 p4 = pr[q4];
            int o = q4 * 4;
            float d;
            d = e4.x - tsm[(g * 16 + o + 0) * 64 + j]; lp = fmaf(d, d, lp);
            d = e4.y - tsm[(g * 16 + o + 1) * 64 + j]; lp = fmaf(d, d, lp);
            d = e4.z - tsm[(g * 16 + o + 2) * 64 + j]; lp = fmaf(d, d, lp);
            d = e4.w - tsm[(g * 16 + o + 3) * 64 + j]; lp = fmaf(d, d, lp);
            op[(size_t)(o + 0) * SPA] = p4.x;
            op[(size_t)(o + 1) * SPA] = p4.y;
            op[(size_t)(o + 2) * SPA] = p4.z;
            op[(size_t)(o + 3) * SPA] = p4.w;
        }
        lsm[g * 64 + j] = lp;
        if (g == 0) dout[OUT_ELEMS + 2 + n0 + j] = (float)myidx;
    }
    __syncthreads();
    if (tid < 64) {
        float s = lsm[tid] + lsm[64 + tid] + lsm[128 + tid] + lsm[192 + tid];
        rv[tid] = s;
    }
    __syncthreads();
    if (tid == 0) {
        float s = 0.0f;
#pragma unroll
        for (int j = 0; j < 64; j++) s += rv[j];
        g_part[blockIdx.x] = s;
    }
}

// ============================================================================
// kD: deterministic final loss reduction over 1024 block partials
// ============================================================================
__global__ void kD(float* __restrict__ dout) {
    __shared__ float red[256];
    int tid = threadIdx.x;
    float s = 0.0f;
#pragma unroll
    for (int j = 0; j < 4; j++) s += g_part[tid + j * 256];
    red[tid] = s;
    __syncthreads();
#pragma unroll
    for (int st = 128; st > 0; st >>= 1) {
        if (tid < st) red[tid] += red[tid + st];
        __syncthreads();
    }
    if (tid == 0) {
        float m = red[0] / (float)OUT_ELEMS;
        dout[OUT_ELEMS]     = m;   // codebook_loss
        dout[OUT_ELEMS + 1] = m;   // commitment_loss (same forward value)
    }
}

// ============================================================================
extern "C" void kernel_launch(void* const* d_in, const int* in_sizes, int n_in,
                              void* d_out, int out_size) {
    const float* z      = (const float*)d_in[0];
    const float* emb    = (const float*)d_in[1];
    const float* pre_w  = (const float*)d_in[2];
    const float* pre_b  = (const float*)d_in[3];
    const float* post_w = (const float*)d_in[4];
    const float* post_b = (const float*)d_in[5];
    float* dout = (float*)d_out;

    cudaFuncSetAttribute(kB, cudaFuncAttributeMaxDynamicSharedMemorySize, SMTOT);

    kP<<<KCODE / 4, 256>>>(emb, post_w, post_b);
    kB<<<NBLK, 256, SMTOT>>>(z, emb, pre_w, pre_b, dout);
    kD<<<1, 256>>>(dout);
}

// round 16
// speedup vs baseline: 1.3247x; 1.0640x over previous
#include <cuda_runtime.h>
#include <cstdint>
#include <cfloat>

// Problem constants: z (2,64,8,64,64), embedding (4096,64)
#define CH 64
#define SPA 32768
#define NTOK 65536
#define KCODE 4096
#define OUT_ELEMS 4194304
#define TBLK 64
#define NBLK (NTOK / TBLK)      // 1024

// kB smem byte offsets (16B aligned)
#define OFF_WSM 0               // pre_w [o][c]                  16384
#define OFF_BSM 16384           // pre_b                           256
#define OFF_ZSM 16640           // z tile [64 c][64 tok]         16384
#define OFF_TSM 33024           // t tile [64 c][64 tok]         16384
#define OFF_ESM 49408           // e chunks 2 x [64 c][128 k]    65536
#define OFF_E2  114944          // e2 2 x 128 f                   1024
#define OFF_RV  115968          // argmin vals [8 w][64 t]        2048
#define OFF_RI  118016          // argmin idxs [8 w][64 t]        2048
#define OFF_IDX 120064          // final idx [64]                  256
#define OFF_LSM 120320          // loss partials [4][64]          1024
#define SMTOT   121344          // > 113.5KB => exactly 1 CTA/SM

typedef unsigned long long ull;

// -------- static device scratch (no cudaMalloc allowed) --------
__device__ __align__(16) float g_eT[KCODE / 128][64][128];   // [chunk][c][k]
__device__ __align__(16) float g_e2[KCODE];
__device__ __align__(16) float g_pe[KCODE * CH];             // emb @ post_w^T + post_b
__device__ float g_part[NBLK];

// -------- helpers (proven R2/R10/R14/R15) --------
__device__ __forceinline__ uint32_t smem_u32(const void* p) {
    uint32_t a;
    asm("{ .reg .u64 t; cvta.to.shared.u64 t, %1; cvt.u32.u64 %0, t; }" : "=r"(a) : "l"(p));
    return a;
}
__device__ __forceinline__ void cpa16(uint32_t dst, const void* src) {
    asm volatile("cp.async.cg.shared.global [%0], [%1], 16;" :: "r"(dst), "l"(src) : "memory");
}
#define CP_COMMIT() asm volatile("cp.async.commit_group;" ::: "memory")
#define CP_WAIT0()  asm volatile("cp.async.wait_group 0;" ::: "memory")
#define CP_WAIT1()  asm volatile("cp.async.wait_group 1;" ::: "memory")

__device__ __forceinline__ ull ffma2(ull a, ull b, ull c) {
    ull d;
    asm("fma.rn.f32x2 %0, %1, %2, %3;" : "=l"(d) : "l"(a), "l"(b), "l"(c));
    return d;
}
__device__ __forceinline__ ull dup2(float x) {
    ull d;
    unsigned u = __float_as_uint(x);
    asm("mov.b64 %0, {%1, %2};" : "=l"(d) : "r"(u), "r"(u));
    return d;
}
__device__ __forceinline__ float f2lo(ull v) { return __uint_as_float((unsigned)v); }
__device__ __forceinline__ float f2hi(ull v) { return __uint_as_float((unsigned)(v >> 32)); }

// ============================================================================
// kP: pe = emb @ post_w^T + post_b ; e2 ; transposed codebook g_eT.
// 1024 blocks x 256 thr; 4 codes per block, one shot (measured 14us).
// ============================================================================
__global__ void __launch_bounds__(256) kP(const float* __restrict__ emb,
                                          const float* __restrict__ post_w,
                                          const float* __restrict__ post_b) {
    __shared__ float wsm[64 * 65];
    __shared__ float esm[4][64];
    __shared__ float wred[4][2];
    int tid = threadIdx.x;
    int sub = tid >> 6;
    int o = tid & 63;
    int wh = (tid >> 5) & 1;
    int k = blockIdx.x * 4 + sub;

    for (int i = tid; i < 4096; i += 256)
        wsm[(i >> 6) * 65 + (i & 63)] = post_w[i];

    float v = emb[k * 64 + o];
    esm[sub][o] = v;
    float sq = v * v;
#pragma unroll
    for (int off = 16; off; off >>= 1)
        sq += __shfl_xor_sync(0xffffffffu, sq, off);
    if ((tid & 31) == 0) wred[sub][wh] = sq;
    __syncthreads();

    float acc = post_b[o];
#pragma unroll
    for (int c = 0; c < 64; c++)
        acc = fmaf(esm[sub][c], wsm[o * 65 + c], acc);
    g_pe[k * 64 + o] = acc;
    g_eT[k >> 7][o][k & 127] = v;
    if (o == 0) g_e2[k] = wred[sub][0] + wred[sub][1];
}

// ============================================================================
// kB: fused pre-conv + exact fp32 argmin + loss/gather/output epilogue.
// 1024 CTAs x 256 thr; 64 tokens/CTA; 1 CTA/SM -> 7 waves @98.9%.
// EXPERIMENT: mixed FFMA2/FFMA schedule (13 pair + 6 scalar FMAs per channel)
// to exploit per-instruction banking rt (Model A). Math is bit-identical:
// scalar fmaf chains = the same fp32 FMA sequence as the FFMA2 lanes replaced;
// scalars cover the HIGHEST codes of each stripe -> ascending-k order intact.
// ============================================================================
__global__ void __launch_bounds__(256) kB(const float* __restrict__ z,
                                          const float* __restrict__ emb,
                                          const float* __restrict__ pre_w,
                                          const float* __restrict__ pre_b,
                                          float* __restrict__ dout) {
    extern __shared__ __align__(16) char sm[];
    uint32_t smb = smem_u32(sm);
    float* wsm  = (float*)(sm + OFF_WSM);
    float* bsm  = (float*)(sm + OFF_BSM);
    float* zsm  = (float*)(sm + OFF_ZSM);
    float* tsm  = (float*)(sm + OFF_TSM);
    float* rv   = (float*)(sm + OFF_RV);
    int*   ri   = (int*)  (sm + OFF_RI);
    int*   idxs = (int*)  (sm + OFF_IDX);
    float* lsm  = (float*)(sm + OFF_LSM);

    int tid = threadIdx.x;
    int ty = tid >> 5;              // warp: 16-code stripe
    int tx = tid & 31;              // lane: token pair (2tx, 2tx+1)
    int n0 = blockIdx.x * TBLK;
    int b  = n0 >> 15;
    int s0 = n0 & 32767;

    // ---- prologue cp.async: group0 = {w, b, z, e chunk0, e2_0}; group1 = {chunk1, e2_1}
    const char* zb = (const char*)z + ((size_t)b * (CH * SPA) + s0) * 4;
#pragma unroll
    for (int it = 0; it < 4; it++)
        cpa16(smb + OFF_WSM + (tid + it * 256) * 16, (const char*)pre_w + (tid + it * 256) * 16);
    if (tid < 16) cpa16(smb + OFF_BSM + tid * 16, (const char*)pre_b + tid * 16);
#pragma unroll
    for (int it = 0; it < 4; it++) {
        int ix = tid + it * 256;    // 1024 segs: c = ix>>4, seg = ix&15
        cpa16(smb + OFF_ZSM + ix * 16, zb + (size_t)(ix >> 4) * SPA * 4 + (ix & 15) * 16);
    }
#pragma unroll
    for (int it = 0; it < 8; it++)
        cpa16(smb + OFF_ESM + (tid + it * 256) * 16, (const char*)g_eT + (tid + it * 256) * 16);
    if (tid < 32) cpa16(smb + OFF_E2 + tid * 16, (const char*)g_e2 + tid * 16);
    CP_COMMIT();
#pragma unroll
    for (int it = 0; it < 8; it++)
        cpa16(smb + OFF_ESM + 32768 + (tid + it * 256) * 16,
              (const char*)g_eT + 32768 + (tid + it * 256) * 16);
    if (tid < 32) cpa16(smb + OFF_E2 + 512 + tid * 16, (const char*)(g_e2 + 128) + tid * 16);
    CP_COMMIT();
    CP_WAIT1();                     // group0 landed
    __syncthreads();

    // ---- phase 0: pre-conv for this block's 64 tokens -> tsm[c][tok]
    {
        int g = tid >> 6;           // 0..3 -> 16 output channels
        int j = tid & 63;           // token
        float acc16[16];
#pragma unroll
        for (int o = 0; o < 16; o++) acc16[o] = bsm[g * 16 + o];
#pragma unroll 8
        for (int c = 0; c < 64; c++) {
            float zv = zsm[c * 64 + j];
#pragma unroll
            for (int o = 0; o < 16; o++)
                acc16[o] = fmaf(zv, wsm[(g * 16 + o) * 64 + c], acc16[o]);
        }
#pragma unroll
        for (int o = 0; o < 16; o++) tsm[(g * 16 + o) * 64 + j] = acc16[o];
    }
    __syncthreads();

    // ---- main loop: 32 chunks of 128 codes, exact fp32, double-buffered
    float best0 = FLT_MAX, best1 = FLT_MAX;
    int bi0 = 0x7fffffff, bi1 = 0x7fffffff;

    for (int i = 0; i < 32; i++) {
        if (i < 31) { CP_WAIT1(); } else { CP_WAIT0(); }
        __syncthreads();
        int buf = i & 1;
        const float* erow = (const float*)(sm + OFF_ESM + buf * 32768) + ty * 16;
        const float* e2b  = (const float*)(sm + OFF_E2 + buf * 512);

        // token0: pairs codes 0..13 (7 FFMA2) + scalars codes 14,15
        // token1: pairs codes 0..11 (6 FFMA2) + scalars codes 12..15
        ull a20[7], a21[6];
        float s0a = 0.0f, s0b = 0.0f;
        float s1a = 0.0f, s1b = 0.0f, s1c = 0.0f, s1d = 0.0f;
#pragma unroll
        for (int j = 0; j < 7; j++) a20[j] = 0ull;
#pragma unroll
        for (int j = 0; j < 6; j++) a21[j] = 0ull;

#pragma unroll 8
        for (int c = 0; c < 64; c++) {
            float2 tv = *(const float2*)(tsm + c * 64 + 2 * tx);
            ull td0 = dup2(tv.x);
            ull td1 = dup2(tv.y);
            const ulonglong2* ep = (const ulonglong2*)(erow + c * 128);
            ulonglong2 ea = ep[0];      // codes 0..3 (warp-uniform LDS)
            ulonglong2 eb = ep[1];      // codes 4..7
            const ulonglong2* ep2 = (const ulonglong2*)(erow + c * 128 + 8);
            ulonglong2 ec = ep2[0];     // codes 8..11
            ulonglong2 ed = ep2[1];     // codes 12..15
            // token0 pairs (codes 0..13)
            a20[0] = ffma2(td0, ea.x, a20[0]);
            a20[1] = ffma2(td0, ea.y, a20[1]);
            a20[2] = ffma2(td0, eb.x, a20[2]);
            a20[3] = ffma2(td0, eb.y, a20[3]);
            a20[4] = ffma2(td0, ec.x, a20[4]);
            a20[5] = ffma2(td0, ec.y, a20[5]);
            a20[6] = ffma2(td0, ed.x, a20[6]);
            // token1 pairs (codes 0..11)
            a21[0] = ffma2(td1, ea.x, a21[0]);
            a21[1] = ffma2(td1, ea.y, a21[1]);
            a21[2] = ffma2(td1, eb.x, a21[2]);
            a21[3] = ffma2(td1, eb.y, a21[3]);
            a21[4] = ffma2(td1, ec.x, a21[4]);
            a21[5] = ffma2(td1, ec.y, a21[5]);
            // scalars (same fp32 FMA sequence as the pairs they replace)
            s0a = fmaf(tv.x, f2lo(ed.y), s0a);     // t0, code 14
            s0b = fmaf(tv.x, f2hi(ed.y), s0b);     // t0, code 15
            s1a = fmaf(tv.y, f2lo(ed.x), s1a);     // t1, code 12
            s1b = fmaf(tv.y, f2hi(ed.x), s1b);     // t1, code 13
            s1c = fmaf(tv.y, f2lo(ed.y), s1c);     // t1, code 14
            s1d = fmaf(tv.y, f2hi(ed.y), s1d);     // t1, code 15
        }

        // score = e2 - 2*dot ; ascending k per token, strict < (jnp tie-break)
        int kb = i * 128 + ty * 16;
        // token0: pairs 0..13 then scalars 14,15 (ascending)
#pragma unroll
        for (int j = 0; j < 7; j++) {
            float sA = fmaf(f2lo(a20[j]), -2.0f, e2b[ty * 16 + 2 * j]);
            float sB = fmaf(f2hi(a20[j]), -2.0f, e2b[ty * 16 + 2 * j + 1]);
            if (sA < best0) { best0 = sA; bi0 = kb + 2 * j; }
            if (sB < best0) { best0 = sB; bi0 = kb + 2 * j + 1; }
        }
        {
            float s14 = fmaf(s0a, -2.0f, e2b[ty * 16 + 14]);
            float s15 = fmaf(s0b, -2.0f, e2b[ty * 16 + 15]);
            if (s14 < best0) { best0 = s14; bi0 = kb + 14; }
            if (s15 < best0) { best0 = s15; bi0 = kb + 15; }
        }
        // token1: pairs 0..11 then scalars 12..15 (ascending)
#pragma unroll
        for (int j = 0; j < 6; j++) {
            float sA = fmaf(f2lo(a21[j]), -2.0f, e2b[ty * 16 + 2 * j]);
            float sB = fmaf(f2hi(a21[j]), -2.0f, e2b[ty * 16 + 2 * j + 1]);
            if (sA < best1) { best1 = sA; bi1 = kb + 2 * j; }
            if (sB < best1) { best1 = sB; bi1 = kb + 2 * j + 1; }
        }
        {
            float s12 = fmaf(s1a, -2.0f, e2b[ty * 16 + 12]);
            float s13 = fmaf(s1b, -2.0f, e2b[ty * 16 + 13]);
            float s14 = fmaf(s1c, -2.0f, e2b[ty * 16 + 14]);
            float s15 = fmaf(s1d, -2.0f, e2b[ty * 16 + 15]);
            if (s12 < best1) { best1 = s12; bi1 = kb + 12; }
            if (s13 < best1) { best1 = s13; bi1 = kb + 13; }
            if (s14 < best1) { best1 = s14; bi1 = kb + 14; }
            if (s15 < best1) { best1 = s15; bi1 = kb + 15; }
        }

        __syncthreads();            // all warps done reading buf
        if (i + 2 < 32) {
            const char* es = (const char*)g_eT + (size_t)(i + 2) * 32768;
#pragma unroll
            for (int it = 0; it < 8; it++)
                cpa16(smb + OFF_ESM + buf * 32768 + (tid + it * 256) * 16,
                      es + (tid + it * 256) * 16);
            if (tid < 32)
                cpa16(smb + OFF_E2 + buf * 512 + tid * 16,
                      (const char*)(g_e2 + (i + 2) * 128) + tid * 16);
            CP_COMMIT();
        }
    }

    // ---- cross-warp argmin reduce per token (lowest-index tie-break)
    rv[ty * 64 + 2 * tx]     = best0;
    rv[ty * 64 + 2 * tx + 1] = best1;
    ri[ty * 64 + 2 * tx]     = bi0;
    ri[ty * 64 + 2 * tx + 1] = bi1;
    __syncthreads();
    if (tid < 64) {
        float bv = FLT_MAX;
        int bk = 0x7fffffff;
#pragma unroll
        for (int w = 0; w < 8; w++) {
            float v = rv[w * 64 + tid];
            int k = ri[w * 64 + tid];
            if (v < bv || (v == bv && k < bk)) { bv = v; bk = k; }
        }
        idxs[tid] = bk;
    }
    __syncthreads();

    // ---- fused output epilogue: loss partial + pe gather + idx out
    {
        int g = tid >> 6;           // 16 channels
        int j = tid & 63;           // token
        int myidx = idxs[j];
        const float4* er = (const float4*)(emb + (size_t)myidx * 64 + g * 16);
        const float4* pr = (const float4*)(g_pe + (size_t)myidx * 64 + g * 16);
        float lp = 0.0f;
        float* op = dout + (size_t)b * (CH * SPA) + (size_t)(g * 16) * SPA + s0 + j;
#pragma unroll
        for (int q4 = 0; q4 < 4; q4++) {
            float4 e4 = er[q4];
            float4 p4 = pr[q4];
            int o = q4 * 4;
            float d;
            d = e4.x - tsm[(g * 16 + o + 0) * 64 + j]; lp = fmaf(d, d, lp);
            d = e4.y - tsm[(g * 16 + o + 1) * 64 + j]; lp = fmaf(d, d, lp);
            d = e4.z - tsm[(g * 16 + o + 2) * 64 + j]; lp = fmaf(d, d, lp);
            d = e4.w - tsm[(g * 16 + o + 3) * 64 + j]; lp = fmaf(d, d, lp);
            op[(size_t)(o + 0) * SPA] = p4.x;
            op[(size_t)(o + 1) * SPA] = p4.y;
            op[(size_t)(o + 2) * SPA] = p4.z;
            op[(size_t)(o + 3) * SPA] = p4.w;
        }
        lsm[g * 64 + j] = lp;
        if (g == 0) dout[OUT_ELEMS + 2 + n0 + j] = (float)myidx;
    }
    __syncthreads();
    if (tid < 64) {
        float s = lsm[tid] + lsm[64 + tid] + lsm[128 + tid] + lsm[192 + tid];
        rv[tid] = s;
    }
    __syncthreads();
    if (tid == 0) {
        float s = 0.0f;
#pragma unroll
        for (int j = 0; j < 64; j++) s += rv[j];
        g_part[blockIdx.x] = s;
    }
}

// ============================================================================
// kD: deterministic final loss reduction over 1024 block partials
// ============================================================================
__global__ void kD(float* __restrict__ dout) {
    __shared__ float red[256];
    int tid = threadIdx.x;
    float s = 0.0f;
#pragma unroll
    for (int j = 0; j < 4; j++) s += g_part[tid + j * 256];
    red[tid] = s;
    __syncthreads();
#pragma unroll
    for (int st = 128; st > 0; st >>= 1) {
        if (tid < st) red[tid] += red[tid + st];
        __syncthreads();
    }
    if (tid == 0) {
        float m = red[0] / (float)OUT_ELEMS;
        dout[OUT_ELEMS]     = m;   // codebook_loss
        dout[OUT_ELEMS + 1] = m;   // commitment_loss (same forward value)
    }
}

// ============================================================================
extern "C" void kernel_launch(void* const* d_in, const int* in_sizes, int n_in,
                              void* d_out, int out_size) {
    const float* z      = (const float*)d_in[0];
    const float* emb    = (const float*)d_in[1];
    const float* pre_w  = (const float*)d_in[2];
    const float* pre_b  = (const float*)d_in[3];
    const float* post_w = (const float*)d_in[4];
    const float* post_b = (const float*)d_in[5];
    float* dout = (float*)d_out;

    cudaFuncSetAttribute(kB, cudaFuncAttributeMaxDynamicSharedMemorySize, SMTOT);

    kP<<<KCODE / 4, 256>>>(emb, post_w, post_b);
    kB<<<NBLK, 256, SMTOT>>>(z, emb, pre_w, pre_b, dout);
    kD<<<1, 256>>>(dout);
}